// round 11
// baseline (speedup 1.0000x reference)
#include <cuda_runtime.h>
#include <cstdint>

// GCN FeatureDiscriminator: B=256, V=512, F=256, O=2
// A: streaming pass (proven, HBM-ceiling ~63us @ 81% DRAM).
// B: quarter-batch aggregation, packed f32x2 accumulate, last-CTA-done
//    epilogue (no separate fin kernel).

#define BATCH 256
#define BV 512
#define BF 256
#define NROWS (BATCH * BV)
#define NTHREADS 512
#define NWARP 16
#define GRID_A 304
#define TOTAL_WARPS_A (GRID_A * NWARP)
#define QROWS 128                     // rows per B CTA (quarter batch)

__device__ unsigned g_bits[NROWS * 16];   // 8 MB: 512-bit mask per row
__device__ float    g_dinv[NROWS];
__device__ float2   g_sxw[NROWS];         // dinv[w] * (X[w,:] @ W)
__device__ float    g_part[BATCH * 4];    // per-quarter head partials
__device__ unsigned g_done[BATCH];        // monotonic arrival counters (mod 4)

#define ADDX2(out, a, b) asm("add.rn.f32x2 %0, %1, %2;" : "=l"(out) : "l"(a), "l"(b))
#define PACKX2(out, lo, hi) asm("mov.b64 %0, {%1, %2};" : "=l"(out) : "r"(lo), "r"(hi))
#define UNPACKX2(lo, hi, in) asm("mov.b64 {%0, %1}, %2;" : "=r"(lo), "=r"(hi) : "l"(in))

// ---------------------------------------------------------------------------
// Kernel A: warp per row, grid-stride. (unchanged — HBM-ceiling)
// Bit convention: bits[row][4c+k] bit 'l'  <->  column w = 128*c + 4*l + k
// ---------------------------------------------------------------------------
__global__ __launch_bounds__(NTHREADS, 2)
void gcn_rows_kernel(const float* __restrict__ features,
                     const int*   __restrict__ graphs,
                     const float* __restrict__ conv_weight)   // [F,2]
{
    const int tid  = threadIdx.x;
    const int wid  = tid >> 5;
    const int lane = tid & 31;
    const int gwarp = blockIdx.x * NWARP + wid;

    float w0r[8], w1r[8];
    {
        const float2* cw2 = (const float2*)conv_weight;
        #pragma unroll
        for (int j = 0; j < 8; j++) {
            float2 w = __ldg(cw2 + 8 * lane + j);
            w0r[j] = w.x; w1r[j] = w.y;
        }
    }

    for (int row = gwarp; row < NROWS; row += TOTAL_WARPS_A) {
        const int v = row & (BV - 1);
        const int4*   grow = (const int4*)graphs + (size_t)row * (BV / 4);
        const float4* frow = (const float4*)features + (size_t)row * (BF / 4);

        int4 x0 = __ldcs(grow + 0 * 32 + lane);
        int4 x1 = __ldcs(grow + 1 * 32 + lane);
        int4 x2 = __ldcs(grow + 2 * 32 + lane);
        int4 x3 = __ldcs(grow + 3 * 32 + lane);
        float4 fa = __ldcs(frow + 2 * lane);
        float4 fb = __ldcs(frow + 2 * lane + 1);

        int deg = 0;
        #pragma unroll
        for (int c = 0; c < 4; c++) {
            int4 x = (c == 0) ? x0 : (c == 1) ? x1 : (c == 2) ? x2 : x3;
            int w0 = 128 * c + 4 * lane;
            unsigned m0 = __ballot_sync(0xffffffffu, (x.x != 0) || (w0     == v));
            unsigned m1 = __ballot_sync(0xffffffffu, (x.y != 0) || (w0 + 1 == v));
            unsigned m2 = __ballot_sync(0xffffffffu, (x.z != 0) || (w0 + 2 == v));
            unsigned m3 = __ballot_sync(0xffffffffu, (x.w != 0) || (w0 + 3 == v));
            deg += __popc(m0) + __popc(m1) + __popc(m2) + __popc(m3);
            if (lane == c) {
                ((uint4*)g_bits)[(size_t)row * 4 + c] = make_uint4(m0, m1, m2, m3);
            }
        }

        float acc0 = fa.x * w0r[0];             float acc1 = fa.x * w1r[0];
        acc0 = fmaf(fa.y, w0r[1], acc0);        acc1 = fmaf(fa.y, w1r[1], acc1);
        acc0 = fmaf(fa.z, w0r[2], acc0);        acc1 = fmaf(fa.z, w1r[2], acc1);
        acc0 = fmaf(fa.w, w0r[3], acc0);        acc1 = fmaf(fa.w, w1r[3], acc1);
        acc0 = fmaf(fb.x, w0r[4], acc0);        acc1 = fmaf(fb.x, w1r[4], acc1);
        acc0 = fmaf(fb.y, w0r[5], acc0);        acc1 = fmaf(fb.y, w1r[5], acc1);
        acc0 = fmaf(fb.z, w0r[6], acc0);        acc1 = fmaf(fb.z, w1r[6], acc1);
        acc0 = fmaf(fb.w, w0r[7], acc0);        acc1 = fmaf(fb.w, w1r[7], acc1);
        #pragma unroll
        for (int s = 16; s; s >>= 1) {
            acc0 += __shfl_xor_sync(0xffffffffu, acc0, s);
            acc1 += __shfl_xor_sync(0xffffffffu, acc1, s);
        }
        if (lane == 0) {
            float d = rsqrtf((float)deg);        // deg >= 1 (self-loop)
            g_dinv[row] = d;
            g_sxw[row]  = make_float2(d * acc0, d * acc1);
        }
    }
}

// ---------------------------------------------------------------------------
// Kernel B: quarter-batch per CTA. 1024 CTAs x 128 threads, occ 8.
// blockIdx.x = 4*b + q ; rows [128q, 128q+128) of batch b.
// Last-arriving CTA of each batch does the final sum + sigmoid.
// ---------------------------------------------------------------------------
__global__ __launch_bounds__(128, 8)
void gcn_agg_kernel(const float* __restrict__ conv_bias,
                    const float* __restrict__ lin_weight,    // [2v+o]
                    const float* __restrict__ lin_bias,
                    float* __restrict__ out)
{
    __shared__ unsigned bits[QROWS][16];   // 8 KB
    __shared__ unsigned long long s2[BV];  // 4 KB: packed (s0,s1)
    __shared__ float dinv_s[QROWS];        // 0.5 KB
    __shared__ float2 lw2[QROWS];          // 1 KB
    __shared__ float wpart[4];

    const int b    = blockIdx.x >> 2;
    const int q    = blockIdx.x & 3;
    const int tid  = threadIdx.x;
    const int wid  = tid >> 5;             // 0..3
    const int lane = tid & 31;
    const unsigned lanebit = 1u << lane;

    // ---- stage (coalesced) ----
    {
        const uint4* src = (const uint4*)g_bits + (size_t)b * (BV * 4)
                         + (size_t)q * (QROWS * 4);
        #pragma unroll
        for (int i = 0; i < 4; i++)
            ((uint4*)bits)[tid + i * 128] = src[tid + i * 128];

        #pragma unroll
        for (int i = 0; i < 4; i++)
            s2[tid + i * 128] =
                ((const unsigned long long*)g_sxw)[b * BV + tid + i * 128];
        dinv_s[tid] = g_dinv[b * BV + q * QROWS + tid];
        lw2[tid]    = ((const float2*)lin_weight)[q * QROWS + tid];
    }
    __syncthreads();

    // preload this lane's fixed 16 packed s pairs: w = 128*c + 4*lane + k
    unsigned long long rp[16];
    #pragma unroll
    for (int c = 0; c < 4; c++)
        #pragma unroll
        for (int k = 0; k < 4; k++)
            rp[4 * c + k] = s2[128 * c + 4 * lane + k];

    const float cb0 = conv_bias[0];
    const float cb1 = conv_bias[1];

    float part = 0.0f;
    #pragma unroll 2
    for (int r = 0; r < QROWS / 4; r++) {          // 32 rows per warp
        const int v = (wid << 5) + r;              // local row
        unsigned long long acc = 0;
        #pragma unroll
        for (int j = 0; j < 16; j++) {
            unsigned m = bits[v][j];               // broadcast LDS
            if (m & lanebit) {                     // LOP3 -> pred, 1 FADD2
                ADDX2(acc, acc, rp[j]);
            }
        }
        unsigned lo_u, hi_u;
        UNPACKX2(lo_u, hi_u, acc);
        float acc0 = __uint_as_float(lo_u), acc1 = __uint_as_float(hi_u);
        #pragma unroll
        for (int s = 16; s; s >>= 1) {
            acc0 += __shfl_xor_sync(0xffffffffu, acc0, s);
            acc1 += __shfl_xor_sync(0xffffffffu, acc1, s);
        }
        if (lane == 0) {
            float d   = dinv_s[v];
            float2 lw = lw2[v];
            float h0 = fmaxf(fmaf(d, acc0, cb0), 0.0f);
            float h1 = fmaxf(fmaf(d, acc1, cb1), 0.0f);
            part = fmaf(h0, lw.x, part);
            part = fmaf(h1, lw.y, part);
        }
    }
    if (lane == 0) wpart[wid] = part;
    __syncthreads();

    // ---- publish partial; 4th arrival finishes the batch ----
    if (tid == 0) {
        g_part[blockIdx.x] = (wpart[0] + wpart[1]) + (wpart[2] + wpart[3]);
        __threadfence();                                    // release partial
        unsigned old = atomicAdd(&g_done[b], 1u);
        if ((old & 3u) == 3u) {                             // monotonic mod-4
            __threadfence();                                // acquire partials
            const float* p = &g_part[b * 4];
            float logit = (p[0] + p[1]) + (p[2] + p[3]) + lin_bias[0];
            out[b] = 1.0f / (1.0f + expf(-logit));
        }
    }
}

extern "C" void kernel_launch(void* const* d_in, const int* in_sizes, int n_in,
                              void* d_out, int out_size) {
    const float* features    = (const float*)d_in[0];
    const int*   graphs      = (const int*)  d_in[1];
    const float* conv_weight = (const float*)d_in[2];
    const float* conv_bias   = (const float*)d_in[3];
    const float* lin_weight  = (const float*)d_in[4];
    const float* lin_bias    = (const float*)d_in[5];
    float* out = (float*)d_out;

    gcn_rows_kernel<<<GRID_A, NTHREADS>>>(features, graphs, conv_weight);
    gcn_agg_kernel<<<BATCH * 4, 128>>>(conv_bias, lin_weight, lin_bias, out);
}

// round 13
// speedup vs baseline: 1.0215x; 1.0215x over previous
#include <cuda_runtime.h>
#include <cstdint>

// GCN FeatureDiscriminator: B=256, V=512, F=256, O=2
// A: streaming pass. graphs (256MB) evict-first; features (128MB) kept
//    L2-resident across graph replays via 256-bit ld.global.nc.L2::evict_last
//    (sm_103 requires .v8.f32 width for the evict_last modifier).
//    bits written with streaming stores (no L2 pollution).
// B: quarter-batch aggregation (exact round-10 proven form) + fin kernel.

#define BATCH 256
#define BV 512
#define BF 256
#define NROWS (BATCH * BV)
#define NTHREADS 512
#define NWARP 16
#define GRID_A 304
#define TOTAL_WARPS_A (GRID_A * NWARP)
#define QROWS 128                     // rows per B CTA (quarter batch)

__device__ unsigned g_bits[NROWS * 16];   // 8 MB: 512-bit mask per row
__device__ float    g_dinv[NROWS];
__device__ float2   g_sxw[NROWS];         // dinv[w] * (X[w,:] @ W)
__device__ float    g_part[BATCH * 4];    // per-quarter head partials

// 256-bit L2-persistent load: 8 floats, evict_last at L2.
__device__ __forceinline__ void ldg_el_v8(const float* p, float4& a, float4& b) {
    asm volatile(
        "ld.global.nc.L2::evict_last.v8.f32 {%0,%1,%2,%3,%4,%5,%6,%7}, [%8];"
        : "=f"(a.x), "=f"(a.y), "=f"(a.z), "=f"(a.w),
          "=f"(b.x), "=f"(b.y), "=f"(b.z), "=f"(b.w)
        : "l"(p));
}

// ---------------------------------------------------------------------------
// Kernel A: warp per row, grid-stride.
// Bit convention: bits[row][4c+k] bit 'l'  <->  column w = 128*c + 4*l + k
// ---------------------------------------------------------------------------
__global__ __launch_bounds__(NTHREADS, 2)
void gcn_rows_kernel(const float* __restrict__ features,
                     const int*   __restrict__ graphs,
                     const float* __restrict__ conv_weight)   // [F,2]
{
    const int tid  = threadIdx.x;
    const int wid  = tid >> 5;
    const int lane = tid & 31;
    const int gwarp = blockIdx.x * NWARP + wid;

    float w0r[8], w1r[8];
    {
        const float2* cw2 = (const float2*)conv_weight;
        #pragma unroll
        for (int j = 0; j < 8; j++) {
            float2 w = __ldg(cw2 + 8 * lane + j);
            w0r[j] = w.x; w1r[j] = w.y;
        }
    }

    for (int row = gwarp; row < NROWS; row += TOTAL_WARPS_A) {
        const int v = row & (BV - 1);
        const int4*  grow = (const int4*)graphs + (size_t)row * (BV / 4);
        const float* frow = features + (size_t)row * BF;

        // graphs: pure stream, evict-first everywhere
        int4 x0 = __ldcs(grow + 0 * 32 + lane);
        int4 x1 = __ldcs(grow + 1 * 32 + lane);
        int4 x2 = __ldcs(grow + 2 * 32 + lane);
        int4 x3 = __ldcs(grow + 3 * 32 + lane);
        // features: one 256-bit load, L2 evict_last -> resident across replays
        float4 fa, fb;
        ldg_el_v8(frow + 8 * lane, fa, fb);

        int deg = 0;
        #pragma unroll
        for (int c = 0; c < 4; c++) {
            int4 x = (c == 0) ? x0 : (c == 1) ? x1 : (c == 2) ? x2 : x3;
            int w0 = 128 * c + 4 * lane;
            unsigned m0 = __ballot_sync(0xffffffffu, (x.x != 0) || (w0     == v));
            unsigned m1 = __ballot_sync(0xffffffffu, (x.y != 0) || (w0 + 1 == v));
            unsigned m2 = __ballot_sync(0xffffffffu, (x.z != 0) || (w0 + 2 == v));
            unsigned m3 = __ballot_sync(0xffffffffu, (x.w != 0) || (w0 + 3 == v));
            deg += __popc(m0) + __popc(m1) + __popc(m2) + __popc(m3);
            if (lane == c) {
                // streaming store: don't let scratch evict features from L2
                __stcs((uint4*)g_bits + (size_t)row * 4 + c,
                       make_uint4(m0, m1, m2, m3));
            }
        }

        float acc0 = fa.x * w0r[0];             float acc1 = fa.x * w1r[0];
        acc0 = fmaf(fa.y, w0r[1], acc0);        acc1 = fmaf(fa.y, w1r[1], acc1);
        acc0 = fmaf(fa.z, w0r[2], acc0);        acc1 = fmaf(fa.z, w1r[2], acc1);
        acc0 = fmaf(fa.w, w0r[3], acc0);        acc1 = fmaf(fa.w, w1r[3], acc1);
        acc0 = fmaf(fb.x, w0r[4], acc0);        acc1 = fmaf(fb.x, w1r[4], acc1);
        acc0 = fmaf(fb.y, w0r[5], acc0);        acc1 = fmaf(fb.y, w1r[5], acc1);
        acc0 = fmaf(fb.z, w0r[6], acc0);        acc1 = fmaf(fb.z, w1r[6], acc1);
        acc0 = fmaf(fb.w, w0r[7], acc0);        acc1 = fmaf(fb.w, w1r[7], acc1);
        #pragma unroll
        for (int s = 16; s; s >>= 1) {
            acc0 += __shfl_xor_sync(0xffffffffu, acc0, s);
            acc1 += __shfl_xor_sync(0xffffffffu, acc1, s);
        }
        if (lane == 0) {
            float d = rsqrtf((float)deg);        // deg >= 1 (self-loop)
            g_dinv[row] = d;
            g_sxw[row]  = make_float2(d * acc0, d * acc1);
        }
    }
}

// ---------------------------------------------------------------------------
// Kernel B: quarter-batch per CTA. 1024 CTAs x 128 threads, occ 8.
// (exact round-10 proven form)
// ---------------------------------------------------------------------------
__global__ __launch_bounds__(128, 8)
void gcn_agg_kernel(const float* __restrict__ conv_bias,
                    const float* __restrict__ lin_weight)    // [2v+o]
{
    __shared__ unsigned bits[QROWS][16];   // 8 KB
    __shared__ float s0[BV];               // 2 KB
    __shared__ float s1[BV];               // 2 KB
    __shared__ float dinv_s[QROWS];        // 0.5 KB
    __shared__ float2 lw2[QROWS];          // 1 KB
    __shared__ float wpart[4];

    const int b    = blockIdx.x >> 2;
    const int q    = blockIdx.x & 3;
    const int tid  = threadIdx.x;
    const int wid  = tid >> 5;             // 0..3
    const int lane = tid & 31;
    const unsigned lanebit = 1u << lane;

    // ---- stage (coalesced) ----
    {
        const uint4* src = (const uint4*)g_bits + (size_t)b * (BV * 4)
                         + (size_t)q * (QROWS * 4);
        #pragma unroll
        for (int i = 0; i < 4; i++)
            ((uint4*)bits)[tid + i * 128] = src[tid + i * 128];

        #pragma unroll
        for (int i = 0; i < 4; i++) {
            float2 t = g_sxw[b * BV + tid + i * 128];   // already dinv-scaled
            s0[tid + i * 128] = t.x;
            s1[tid + i * 128] = t.y;
        }
        dinv_s[tid] = g_dinv[b * BV + q * QROWS + tid];
        lw2[tid]    = ((const float2*)lin_weight)[q * QROWS + tid];
    }
    __syncthreads();

    // preload this lane's fixed 16 s pairs: w = 128*c + 4*lane + k
    float r0[16], r1[16];
    #pragma unroll
    for (int c = 0; c < 4; c++)
        #pragma unroll
        for (int k = 0; k < 4; k++) {
            int w = 128 * c + 4 * lane + k;
            r0[4 * c + k] = s0[w];
            r1[4 * c + k] = s1[w];
        }

    const float cb0 = conv_bias[0];
    const float cb1 = conv_bias[1];

    float part = 0.0f;
    #pragma unroll 2
    for (int r = 0; r < QROWS / 4; r++) {          // 32 rows per warp
        const int v = (wid << 5) + r;              // local row
        float acc0 = 0.0f, acc1 = 0.0f;
        #pragma unroll
        for (int j = 0; j < 16; j++) {
            unsigned m = bits[v][j];               // broadcast LDS
            if (m & lanebit) {                     // single LOP3 -> pred
                acc0 += r0[j];
                acc1 += r1[j];
            }
        }
        #pragma unroll
        for (int s = 16; s; s >>= 1) {
            acc0 += __shfl_xor_sync(0xffffffffu, acc0, s);
            acc1 += __shfl_xor_sync(0xffffffffu, acc1, s);
        }
        if (lane == 0) {
            float d   = dinv_s[v];
            float2 lw = lw2[v];
            float h0 = fmaxf(fmaf(d, acc0, cb0), 0.0f);
            float h1 = fmaxf(fmaf(d, acc1, cb1), 0.0f);
            part = fmaf(h0, lw.x, part);
            part = fmaf(h1, lw.y, part);
        }
    }
    if (lane == 0) wpart[wid] = part;
    __syncthreads();

    if (tid == 0)
        g_part[blockIdx.x] = (wpart[0] + wpart[1]) + (wpart[2] + wpart[3]);
}

// ---------------------------------------------------------------------------
// Final: sum 4 quarter-partials per batch + bias, sigmoid.
// ---------------------------------------------------------------------------
__global__ void gcn_fin_kernel(const float* __restrict__ lin_bias,
                               float* __restrict__ out)
{
    int b = threadIdx.x;
    float4 p = ((const float4*)g_part)[b];
    float logit = (p.x + p.y) + (p.z + p.w) + lin_bias[0];
    out[b] = 1.0f / (1.0f + expf(-logit));
}

extern "C" void kernel_launch(void* const* d_in, const int* in_sizes, int n_in,
                              void* d_out, int out_size) {
    const float* features    = (const float*)d_in[0];
    const int*   graphs      = (const int*)  d_in[1];
    const float* conv_weight = (const float*)d_in[2];
    const float* conv_bias   = (const float*)d_in[3];
    const float* lin_weight  = (const float*)d_in[4];
    const float* lin_bias    = (const float*)d_in[5];
    float* out = (float*)d_out;

    gcn_rows_kernel<<<GRID_A, NTHREADS>>>(features, graphs, conv_weight);
    gcn_agg_kernel<<<BATCH * 4, 128>>>(conv_bias, lin_weight);
    gcn_fin_kernel<<<1, BATCH>>>(lin_bias, out);
}

// round 14
// speedup vs baseline: 1.0222x; 1.0008x over previous
#include <cuda_runtime.h>
#include <cstdint>

// GCN FeatureDiscriminator: B=256, V=512, F=256, O=2
// A: streaming pass (round-10 exact form — measured at the HBM/LTS ceiling).
// B: quarter-batch aggregation; round-10 loop with ONE isolated change
//    (LDS.128 mask loads) + last-CTA-done epilogue (no fin kernel).

#define BATCH 256
#define BV 512
#define BF 256
#define NROWS (BATCH * BV)
#define NTHREADS 512
#define NWARP 16
#define GRID_A 304
#define TOTAL_WARPS_A (GRID_A * NWARP)
#define QROWS 128                     // rows per B CTA (quarter batch)

__device__ unsigned g_bits[NROWS * 16];   // 8 MB: 512-bit mask per row
__device__ float    g_dinv[NROWS];
__device__ float2   g_sxw[NROWS];         // dinv[w] * (X[w,:] @ W)
__device__ float    g_part[BATCH * 4];    // per-quarter head partials
__device__ unsigned g_done[BATCH];        // monotonic arrival counters (mod 4)

// ---------------------------------------------------------------------------
// Kernel A: warp per row, grid-stride. (round-10 exact — proven ceiling)
// Bit convention: bits[row][4c+k] bit 'l'  <->  column w = 128*c + 4*l + k
// ---------------------------------------------------------------------------
__global__ __launch_bounds__(NTHREADS, 2)
void gcn_rows_kernel(const float* __restrict__ features,
                     const int*   __restrict__ graphs,
                     const float* __restrict__ conv_weight)   // [F,2]
{
    const int tid  = threadIdx.x;
    const int wid  = tid >> 5;
    const int lane = tid & 31;
    const int gwarp = blockIdx.x * NWARP + wid;

    float w0r[8], w1r[8];
    {
        const float2* cw2 = (const float2*)conv_weight;
        #pragma unroll
        for (int j = 0; j < 8; j++) {
            float2 w = __ldg(cw2 + 8 * lane + j);
            w0r[j] = w.x; w1r[j] = w.y;
        }
    }

    for (int row = gwarp; row < NROWS; row += TOTAL_WARPS_A) {
        const int v = row & (BV - 1);
        const int4*   grow = (const int4*)graphs + (size_t)row * (BV / 4);
        const float4* frow = (const float4*)features + (size_t)row * (BF / 4);

        int4 x0 = __ldcs(grow + 0 * 32 + lane);
        int4 x1 = __ldcs(grow + 1 * 32 + lane);
        int4 x2 = __ldcs(grow + 2 * 32 + lane);
        int4 x3 = __ldcs(grow + 3 * 32 + lane);
        float4 fa = __ldcs(frow + 2 * lane);
        float4 fb = __ldcs(frow + 2 * lane + 1);

        int deg = 0;
        #pragma unroll
        for (int c = 0; c < 4; c++) {
            int4 x = (c == 0) ? x0 : (c == 1) ? x1 : (c == 2) ? x2 : x3;
            int w0 = 128 * c + 4 * lane;
            unsigned m0 = __ballot_sync(0xffffffffu, (x.x != 0) || (w0     == v));
            unsigned m1 = __ballot_sync(0xffffffffu, (x.y != 0) || (w0 + 1 == v));
            unsigned m2 = __ballot_sync(0xffffffffu, (x.z != 0) || (w0 + 2 == v));
            unsigned m3 = __ballot_sync(0xffffffffu, (x.w != 0) || (w0 + 3 == v));
            deg += __popc(m0) + __popc(m1) + __popc(m2) + __popc(m3);
            if (lane == c) {
                ((uint4*)g_bits)[(size_t)row * 4 + c] = make_uint4(m0, m1, m2, m3);
            }
        }

        float acc0 = fa.x * w0r[0];             float acc1 = fa.x * w1r[0];
        acc0 = fmaf(fa.y, w0r[1], acc0);        acc1 = fmaf(fa.y, w1r[1], acc1);
        acc0 = fmaf(fa.z, w0r[2], acc0);        acc1 = fmaf(fa.z, w1r[2], acc1);
        acc0 = fmaf(fa.w, w0r[3], acc0);        acc1 = fmaf(fa.w, w1r[3], acc1);
        acc0 = fmaf(fb.x, w0r[4], acc0);        acc1 = fmaf(fb.x, w1r[4], acc1);
        acc0 = fmaf(fb.y, w0r[5], acc0);        acc1 = fmaf(fb.y, w1r[5], acc1);
        acc0 = fmaf(fb.z, w0r[6], acc0);        acc1 = fmaf(fb.z, w1r[6], acc1);
        acc0 = fmaf(fb.w, w0r[7], acc0);        acc1 = fmaf(fb.w, w1r[7], acc1);
        #pragma unroll
        for (int s = 16; s; s >>= 1) {
            acc0 += __shfl_xor_sync(0xffffffffu, acc0, s);
            acc1 += __shfl_xor_sync(0xffffffffu, acc1, s);
        }
        if (lane == 0) {
            float d = rsqrtf((float)deg);        // deg >= 1 (self-loop)
            g_dinv[row] = d;
            g_sxw[row]  = make_float2(d * acc0, d * acc1);
        }
    }
}

// ---------------------------------------------------------------------------
// Kernel B: quarter-batch per CTA. 1024 CTAs x 128 threads, occ 8.
// Round-10 body; isolated change: 4x LDS.128 mask loads. Last-arriving CTA
// of each batch sums the 4 partials + sigmoid (no fin kernel).
// ---------------------------------------------------------------------------
__global__ __launch_bounds__(128, 8)
void gcn_agg_kernel(const float* __restrict__ conv_bias,
                    const float* __restrict__ lin_weight,    // [2v+o]
                    const float* __restrict__ lin_bias,
                    float* __restrict__ out)
{
    __shared__ unsigned bits[QROWS][16];   // 8 KB
    __shared__ float s0[BV];               // 2 KB
    __shared__ float s1[BV];               // 2 KB
    __shared__ float dinv_s[QROWS];        // 0.5 KB
    __shared__ float2 lw2[QROWS];          // 1 KB
    __shared__ float wpart[4];

    const int b    = blockIdx.x >> 2;
    const int q    = blockIdx.x & 3;
    const int tid  = threadIdx.x;
    const int wid  = tid >> 5;             // 0..3
    const int lane = tid & 31;
    const unsigned lanebit = 1u << lane;

    // ---- stage (coalesced) ----
    {
        const uint4* src = (const uint4*)g_bits + (size_t)b * (BV * 4)
                         + (size_t)q * (QROWS * 4);
        #pragma unroll
        for (int i = 0; i < 4; i++)
            ((uint4*)bits)[tid + i * 128] = src[tid + i * 128];

        #pragma unroll
        for (int i = 0; i < 4; i++) {
            float2 t = g_sxw[b * BV + tid + i * 128];   // already dinv-scaled
            s0[tid + i * 128] = t.x;
            s1[tid + i * 128] = t.y;
        }
        dinv_s[tid] = g_dinv[b * BV + q * QROWS + tid];
        lw2[tid]    = ((const float2*)lin_weight)[q * QROWS + tid];
    }
    __syncthreads();

    // preload this lane's fixed 16 s pairs: w = 128*c + 4*lane + k
    float r0[16], r1[16];
    #pragma unroll
    for (int c = 0; c < 4; c++)
        #pragma unroll
        for (int k = 0; k < 4; k++) {
            int w = 128 * c + 4 * lane + k;
            r0[4 * c + k] = s0[w];
            r1[4 * c + k] = s1[w];
        }

    const float cb0 = conv_bias[0];
    const float cb1 = conv_bias[1];

    float part = 0.0f;
    #pragma unroll 2
    for (int r = 0; r < QROWS / 4; r++) {          // 32 rows per warp
        const int v = (wid << 5) + r;              // local row
        const uint4* bw = (const uint4*)bits[v];   // broadcast LDS.128 x4
        uint4 q0 = bw[0], q1 = bw[1], q2 = bw[2], q3 = bw[3];
        float acc0 = 0.0f, acc1 = 0.0f;
        if (q0.x & lanebit) { acc0 += r0[0];  acc1 += r1[0];  }
        if (q0.y & lanebit) { acc0 += r0[1];  acc1 += r1[1];  }
        if (q0.z & lanebit) { acc0 += r0[2];  acc1 += r1[2];  }
        if (q0.w & lanebit) { acc0 += r0[3];  acc1 += r1[3];  }
        if (q1.x & lanebit) { acc0 += r0[4];  acc1 += r1[4];  }
        if (q1.y & lanebit) { acc0 += r0[5];  acc1 += r1[5];  }
        if (q1.z & lanebit) { acc0 += r0[6];  acc1 += r1[6];  }
        if (q1.w & lanebit) { acc0 += r0[7];  acc1 += r1[7];  }
        if (q2.x & lanebit) { acc0 += r0[8];  acc1 += r1[8];  }
        if (q2.y & lanebit) { acc0 += r0[9];  acc1 += r1[9];  }
        if (q2.z & lanebit) { acc0 += r0[10]; acc1 += r1[10]; }
        if (q2.w & lanebit) { acc0 += r0[11]; acc1 += r1[11]; }
        if (q3.x & lanebit) { acc0 += r0[12]; acc1 += r1[12]; }
        if (q3.y & lanebit) { acc0 += r0[13]; acc1 += r1[13]; }
        if (q3.z & lanebit) { acc0 += r0[14]; acc1 += r1[14]; }
        if (q3.w & lanebit) { acc0 += r0[15]; acc1 += r1[15]; }
        #pragma unroll
        for (int s = 16; s; s >>= 1) {
            acc0 += __shfl_xor_sync(0xffffffffu, acc0, s);
            acc1 += __shfl_xor_sync(0xffffffffu, acc1, s);
        }
        if (lane == 0) {
            float d   = dinv_s[v];
            float2 lw = lw2[v];
            float h0 = fmaxf(fmaf(d, acc0, cb0), 0.0f);
            float h1 = fmaxf(fmaf(d, acc1, cb1), 0.0f);
            part = fmaf(h0, lw.x, part);
            part = fmaf(h1, lw.y, part);
        }
    }
    if (lane == 0) wpart[wid] = part;
    __syncthreads();

    // ---- publish partial; 4th arrival finishes the batch ----
    if (tid == 0) {
        g_part[blockIdx.x] = (wpart[0] + wpart[1]) + (wpart[2] + wpart[3]);
        __threadfence();                                    // release partial
        unsigned old = atomicAdd(&g_done[b], 1u);
        if ((old & 3u) == 3u) {                             // monotonic mod-4
            __threadfence();                                // acquire partials
            const float* p = &g_part[b * 4];
            float logit = (p[0] + p[1]) + (p[2] + p[3]) + lin_bias[0];
            out[b] = 1.0f / (1.0f + expf(-logit));
        }
    }
}

extern "C" void kernel_launch(void* const* d_in, const int* in_sizes, int n_in,
                              void* d_out, int out_size) {
    const float* features    = (const float*)d_in[0];
    const int*   graphs      = (const int*)  d_in[1];
    const float* conv_weight = (const float*)d_in[2];
    const float* conv_bias   = (const float*)d_in[3];
    const float* lin_weight  = (const float*)d_in[4];
    const float* lin_bias    = (const float*)d_in[5];
    float* out = (float*)d_out;

    gcn_rows_kernel<<<GRID_A, NTHREADS>>>(features, graphs, conv_weight);
    gcn_agg_kernel<<<BATCH * 4, 128>>>(conv_bias, lin_weight, lin_bias, out);
}

// round 15
// speedup vs baseline: 1.0426x; 1.0199x over previous
#include <cuda_runtime.h>
#include <cstdint>

// GCN FeatureDiscriminator: B=256, V=512, F=256, O=2
// A: streaming pass (round-10 exact form — measured at HBM ceiling).
// B: quarter-batch aggregation, scalar-LDS predicated-FADD body (proven best),
//    paired-half reduction (13 slots vs 20), last-CTA-done epilogue.

#define BATCH 256
#define BV 512
#define BF 256
#define NROWS (BATCH * BV)
#define NTHREADS 512
#define NWARP 16
#define GRID_A 304
#define TOTAL_WARPS_A (GRID_A * NWARP)
#define QROWS 128                     // rows per B CTA (quarter batch)

__device__ unsigned g_bits[NROWS * 16];   // 8 MB: 512-bit mask per row
__device__ float    g_dinv[NROWS];
__device__ float2   g_sxw[NROWS];         // dinv[w] * (X[w,:] @ W)
__device__ float    g_part[BATCH * 4];    // per-quarter head partials
__device__ unsigned g_done[BATCH];        // monotonic arrival counters (mod 4)

// ---------------------------------------------------------------------------
// Kernel A: warp per row, grid-stride. (round-10 exact — proven ceiling)
// Bit convention: bits[row][4c+k] bit 'l'  <->  column w = 128*c + 4*l + k
// ---------------------------------------------------------------------------
__global__ __launch_bounds__(NTHREADS, 2)
void gcn_rows_kernel(const float* __restrict__ features,
                     const int*   __restrict__ graphs,
                     const float* __restrict__ conv_weight)   // [F,2]
{
    const int tid  = threadIdx.x;
    const int wid  = tid >> 5;
    const int lane = tid & 31;
    const int gwarp = blockIdx.x * NWARP + wid;

    float w0r[8], w1r[8];
    {
        const float2* cw2 = (const float2*)conv_weight;
        #pragma unroll
        for (int j = 0; j < 8; j++) {
            float2 w = __ldg(cw2 + 8 * lane + j);
            w0r[j] = w.x; w1r[j] = w.y;
        }
    }

    for (int row = gwarp; row < NROWS; row += TOTAL_WARPS_A) {
        const int v = row & (BV - 1);
        const int4*   grow = (const int4*)graphs + (size_t)row * (BV / 4);
        const float4* frow = (const float4*)features + (size_t)row * (BF / 4);

        int4 x0 = __ldcs(grow + 0 * 32 + lane);
        int4 x1 = __ldcs(grow + 1 * 32 + lane);
        int4 x2 = __ldcs(grow + 2 * 32 + lane);
        int4 x3 = __ldcs(grow + 3 * 32 + lane);
        float4 fa = __ldcs(frow + 2 * lane);
        float4 fb = __ldcs(frow + 2 * lane + 1);

        int deg = 0;
        #pragma unroll
        for (int c = 0; c < 4; c++) {
            int4 x = (c == 0) ? x0 : (c == 1) ? x1 : (c == 2) ? x2 : x3;
            int w0 = 128 * c + 4 * lane;
            unsigned m0 = __ballot_sync(0xffffffffu, (x.x != 0) || (w0     == v));
            unsigned m1 = __ballot_sync(0xffffffffu, (x.y != 0) || (w0 + 1 == v));
            unsigned m2 = __ballot_sync(0xffffffffu, (x.z != 0) || (w0 + 2 == v));
            unsigned m3 = __ballot_sync(0xffffffffu, (x.w != 0) || (w0 + 3 == v));
            deg += __popc(m0) + __popc(m1) + __popc(m2) + __popc(m3);
            if (lane == c) {
                ((uint4*)g_bits)[(size_t)row * 4 + c] = make_uint4(m0, m1, m2, m3);
            }
        }

        float acc0 = fa.x * w0r[0];             float acc1 = fa.x * w1r[0];
        acc0 = fmaf(fa.y, w0r[1], acc0);        acc1 = fmaf(fa.y, w1r[1], acc1);
        acc0 = fmaf(fa.z, w0r[2], acc0);        acc1 = fmaf(fa.z, w1r[2], acc1);
        acc0 = fmaf(fa.w, w0r[3], acc0);        acc1 = fmaf(fa.w, w1r[3], acc1);
        acc0 = fmaf(fb.x, w0r[4], acc0);        acc1 = fmaf(fb.x, w1r[4], acc1);
        acc0 = fmaf(fb.y, w0r[5], acc0);        acc1 = fmaf(fb.y, w1r[5], acc1);
        acc0 = fmaf(fb.z, w0r[6], acc0);        acc1 = fmaf(fb.z, w1r[6], acc1);
        acc0 = fmaf(fb.w, w0r[7], acc0);        acc1 = fmaf(fb.w, w1r[7], acc1);
        #pragma unroll
        for (int s = 16; s; s >>= 1) {
            acc0 += __shfl_xor_sync(0xffffffffu, acc0, s);
            acc1 += __shfl_xor_sync(0xffffffffu, acc1, s);
        }
        if (lane == 0) {
            float d = rsqrtf((float)deg);        // deg >= 1 (self-loop)
            g_dinv[row] = d;
            g_sxw[row]  = make_float2(d * acc0, d * acc1);
        }
    }
}

// ---------------------------------------------------------------------------
// Kernel B: quarter-batch per CTA. 1024 CTAs x 128 threads, occ 8.
// Scalar-LDS body (proven); paired-half reduction; last-CTA-done epilogue.
// ---------------------------------------------------------------------------
__global__ __launch_bounds__(128, 8)
void gcn_agg_kernel(const float* __restrict__ conv_bias,
                    const float* __restrict__ lin_weight,    // [2v+o]
                    const float* __restrict__ lin_bias,
                    float* __restrict__ out)
{
    __shared__ unsigned bits[QROWS][16];   // 8 KB
    __shared__ float s0[BV];               // 2 KB
    __shared__ float s1[BV];               // 2 KB
    __shared__ float dinv_s[QROWS];        // 0.5 KB
    __shared__ float2 lw2[QROWS];          // 1 KB
    __shared__ float wpart[8];

    const int b    = blockIdx.x >> 2;
    const int q    = blockIdx.x & 3;
    const int tid  = threadIdx.x;
    const int wid  = tid >> 5;             // 0..3
    const int lane = tid & 31;
    const unsigned lanebit = 1u << lane;
    const bool hi_half = (lane & 16) != 0;

    // ---- stage (coalesced) ----
    {
        const uint4* src = (const uint4*)g_bits + (size_t)b * (BV * 4)
                         + (size_t)q * (QROWS * 4);
        #pragma unroll
        for (int i = 0; i < 4; i++)
            ((uint4*)bits)[tid + i * 128] = src[tid + i * 128];

        #pragma unroll
        for (int i = 0; i < 4; i++) {
            float2 t = g_sxw[b * BV + tid + i * 128];   // already dinv-scaled
            s0[tid + i * 128] = t.x;
            s1[tid + i * 128] = t.y;
        }
        dinv_s[tid] = g_dinv[b * BV + q * QROWS + tid];
        lw2[tid]    = ((const float2*)lin_weight)[q * QROWS + tid];
    }
    __syncthreads();

    // preload this lane's fixed 16 s pairs: w = 128*c + 4*lane + k
    float r0[16], r1[16];
    #pragma unroll
    for (int c = 0; c < 4; c++)
        #pragma unroll
        for (int k = 0; k < 4; k++) {
            int w = 128 * c + 4 * lane + k;
            r0[4 * c + k] = s0[w];
            r1[4 * c + k] = s1[w];
        }

    const float cb0 = conv_bias[0];
    const float cb1 = conv_bias[1];

    float part = 0.0f;
    #pragma unroll 2
    for (int r = 0; r < QROWS / 4; r++) {          // 32 rows per warp
        const int v = (wid << 5) + r;              // local row
        float acc0 = 0.0f, acc1 = 0.0f;
        #pragma unroll
        for (int j = 0; j < 16; j++) {
            unsigned m = bits[v][j];               // broadcast LDS (scalar)
            if (m & lanebit) {                     // single LOP3 -> pred
                acc0 += r0[j];
                acc1 += r1[j];
            }
        }
        // paired-half reduction: lo half ends with sum(acc0), hi with sum(acc1)
        float a = __shfl_xor_sync(0xffffffffu, acc0, 16);
        float bb = __shfl_xor_sync(0xffffffffu, acc1, 16);
        float x = hi_half ? (acc1 + bb) : (acc0 + a);
        #pragma unroll
        for (int s = 8; s; s >>= 1)
            x += __shfl_xor_sync(0xffffffffu, x, s);

        // epilogue on lanes 0 (y0) and 16 (y1)
        if ((lane & 15) == 0) {
            float d   = dinv_s[v];
            float2 lw = lw2[v];
            float cbx = hi_half ? cb1 : cb0;
            float lwx = hi_half ? lw.y : lw.x;
            float h = fmaxf(fmaf(d, x, cbx), 0.0f);
            part = fmaf(h, lwx, part);
        }
    }
    if ((lane & 15) == 0) wpart[wid * 2 + (lane >> 4)] = part;
    __syncthreads();

    // ---- publish partial; 4th arrival finishes the batch ----
    if (tid == 0) {
        float p8 = ((wpart[0] + wpart[1]) + (wpart[2] + wpart[3]))
                 + ((wpart[4] + wpart[5]) + (wpart[6] + wpart[7]));
        g_part[blockIdx.x] = p8;
        __threadfence();                                    // release partial
        unsigned old = atomicAdd(&g_done[b], 1u);
        if ((old & 3u) == 3u) {                             // monotonic mod-4
            __threadfence();                                // acquire partials
            const float* p = &g_part[b * 4];
            float logit = (p[0] + p[1]) + (p[2] + p[3]) + lin_bias[0];
            out[b] = 1.0f / (1.0f + expf(-logit));
        }
    }
}

extern "C" void kernel_launch(void* const* d_in, const int* in_sizes, int n_in,
                              void* d_out, int out_size) {
    const float* features    = (const float*)d_in[0];
    const int*   graphs      = (const int*)  d_in[1];
    const float* conv_weight = (const float*)d_in[2];
    const float* conv_bias   = (const float*)d_in[3];
    const float* lin_weight  = (const float*)d_in[4];
    const float* lin_bias    = (const float*)d_in[5];
    float* out = (float*)d_out;

    gcn_rows_kernel<<<GRID_A, NTHREADS>>>(features, graphs, conv_weight);
    gcn_agg_kernel<<<BATCH * 4, 128>>>(conv_bias, lin_weight, lin_bias, out);
}

// round 16
// speedup vs baseline: 1.0455x; 1.0028x over previous
#include <cuda_runtime.h>
#include <cstdint>

// GCN FeatureDiscriminator: B=256, V=512, F=256, O=2
// A: streaming pass (round-10 exact form — measured at HBM ceiling ~61us).
// B: quarter-batch aggregation, scalar-LDS predicated-FADD body with
//    SPLIT ACCUMULATORS (8-deep chains for ILP), paired-half reduction,
//    last-CTA-done epilogue.

#define BATCH 256
#define BV 512
#define BF 256
#define NROWS (BATCH * BV)
#define NTHREADS 512
#define NWARP 16
#define GRID_A 304
#define TOTAL_WARPS_A (GRID_A * NWARP)
#define QROWS 128                     // rows per B CTA (quarter batch)

__device__ unsigned g_bits[NROWS * 16];   // 8 MB: 512-bit mask per row
__device__ float    g_dinv[NROWS];
__device__ float2   g_sxw[NROWS];         // dinv[w] * (X[w,:] @ W)
__device__ float    g_part[BATCH * 4];    // per-quarter head partials
__device__ unsigned g_done[BATCH];        // monotonic arrival counters (mod 4)

// ---------------------------------------------------------------------------
// Kernel A: warp per row, grid-stride. (round-10 exact — proven ceiling)
// Bit convention: bits[row][4c+k] bit 'l'  <->  column w = 128*c + 4*l + k
// ---------------------------------------------------------------------------
__global__ __launch_bounds__(NTHREADS, 2)
void gcn_rows_kernel(const float* __restrict__ features,
                     const int*   __restrict__ graphs,
                     const float* __restrict__ conv_weight)   // [F,2]
{
    const int tid  = threadIdx.x;
    const int wid  = tid >> 5;
    const int lane = tid & 31;
    const int gwarp = blockIdx.x * NWARP + wid;

    float w0r[8], w1r[8];
    {
        const float2* cw2 = (const float2*)conv_weight;
        #pragma unroll
        for (int j = 0; j < 8; j++) {
            float2 w = __ldg(cw2 + 8 * lane + j);
            w0r[j] = w.x; w1r[j] = w.y;
        }
    }

    for (int row = gwarp; row < NROWS; row += TOTAL_WARPS_A) {
        const int v = row & (BV - 1);
        const int4*   grow = (const int4*)graphs + (size_t)row * (BV / 4);
        const float4* frow = (const float4*)features + (size_t)row * (BF / 4);

        int4 x0 = __ldcs(grow + 0 * 32 + lane);
        int4 x1 = __ldcs(grow + 1 * 32 + lane);
        int4 x2 = __ldcs(grow + 2 * 32 + lane);
        int4 x3 = __ldcs(grow + 3 * 32 + lane);
        float4 fa = __ldcs(frow + 2 * lane);
        float4 fb = __ldcs(frow + 2 * lane + 1);

        int deg = 0;
        #pragma unroll
        for (int c = 0; c < 4; c++) {
            int4 x = (c == 0) ? x0 : (c == 1) ? x1 : (c == 2) ? x2 : x3;
            int w0 = 128 * c + 4 * lane;
            unsigned m0 = __ballot_sync(0xffffffffu, (x.x != 0) || (w0     == v));
            unsigned m1 = __ballot_sync(0xffffffffu, (x.y != 0) || (w0 + 1 == v));
            unsigned m2 = __ballot_sync(0xffffffffu, (x.z != 0) || (w0 + 2 == v));
            unsigned m3 = __ballot_sync(0xffffffffu, (x.w != 0) || (w0 + 3 == v));
            deg += __popc(m0) + __popc(m1) + __popc(m2) + __popc(m3);
            if (lane == c) {
                ((uint4*)g_bits)[(size_t)row * 4 + c] = make_uint4(m0, m1, m2, m3);
            }
        }

        float acc0 = fa.x * w0r[0];             float acc1 = fa.x * w1r[0];
        acc0 = fmaf(fa.y, w0r[1], acc0);        acc1 = fmaf(fa.y, w1r[1], acc1);
        acc0 = fmaf(fa.z, w0r[2], acc0);        acc1 = fmaf(fa.z, w1r[2], acc1);
        acc0 = fmaf(fa.w, w0r[3], acc0);        acc1 = fmaf(fa.w, w1r[3], acc1);
        acc0 = fmaf(fb.x, w0r[4], acc0);        acc1 = fmaf(fb.x, w1r[4], acc1);
        acc0 = fmaf(fb.y, w0r[5], acc0);        acc1 = fmaf(fb.y, w1r[5], acc1);
        acc0 = fmaf(fb.z, w0r[6], acc0);        acc1 = fmaf(fb.z, w1r[6], acc1);
        acc0 = fmaf(fb.w, w0r[7], acc0);        acc1 = fmaf(fb.w, w1r[7], acc1);
        #pragma unroll
        for (int s = 16; s; s >>= 1) {
            acc0 += __shfl_xor_sync(0xffffffffu, acc0, s);
            acc1 += __shfl_xor_sync(0xffffffffu, acc1, s);
        }
        if (lane == 0) {
            float d = rsqrtf((float)deg);        // deg >= 1 (self-loop)
            g_dinv[row] = d;
            g_sxw[row]  = make_float2(d * acc0, d * acc1);
        }
    }
}

// ---------------------------------------------------------------------------
// Kernel B: quarter-batch per CTA. 1024 CTAs x 128 threads, occ 8.
// Scalar-LDS body, split accumulators (ILP), paired-half reduction,
// last-CTA-done epilogue.
// ---------------------------------------------------------------------------
__global__ __launch_bounds__(128, 8)
void gcn_agg_kernel(const float* __restrict__ conv_bias,
                    const float* __restrict__ lin_weight,    // [2v+o]
                    const float* __restrict__ lin_bias,
                    float* __restrict__ out)
{
    __shared__ unsigned bits[QROWS][16];   // 8 KB
    __shared__ float s0[BV];               // 2 KB
    __shared__ float s1[BV];               // 2 KB
    __shared__ float dinv_s[QROWS];        // 0.5 KB
    __shared__ float2 lw2[QROWS];          // 1 KB
    __shared__ float wpart[8];

    const int b    = blockIdx.x >> 2;
    const int q    = blockIdx.x & 3;
    const int tid  = threadIdx.x;
    const int wid  = tid >> 5;             // 0..3
    const int lane = tid & 31;
    const unsigned lanebit = 1u << lane;
    const bool hi_half = (lane & 16) != 0;

    // ---- stage (coalesced) ----
    {
        const uint4* src = (const uint4*)g_bits + (size_t)b * (BV * 4)
                         + (size_t)q * (QROWS * 4);
        #pragma unroll
        for (int i = 0; i < 4; i++)
            ((uint4*)bits)[tid + i * 128] = src[tid + i * 128];

        #pragma unroll
        for (int i = 0; i < 4; i++) {
            float2 t = g_sxw[b * BV + tid + i * 128];   // already dinv-scaled
            s0[tid + i * 128] = t.x;
            s1[tid + i * 128] = t.y;
        }
        dinv_s[tid] = g_dinv[b * BV + q * QROWS + tid];
        lw2[tid]    = ((const float2*)lin_weight)[q * QROWS + tid];
    }
    __syncthreads();

    // preload this lane's fixed 16 s pairs: w = 128*c + 4*lane + k
    float r0[16], r1[16];
    #pragma unroll
    for (int c = 0; c < 4; c++)
        #pragma unroll
        for (int k = 0; k < 4; k++) {
            int w = 128 * c + 4 * lane + k;
            r0[4 * c + k] = s0[w];
            r1[4 * c + k] = s1[w];
        }

    const float cb0 = conv_bias[0];
    const float cb1 = conv_bias[1];

    float part = 0.0f;
    #pragma unroll 2
    for (int r = 0; r < QROWS / 4; r++) {          // 32 rows per warp
        const int v = (wid << 5) + r;              // local row
        // split accumulators: two independent 8-deep FADD chains per output
        float a0 = 0.0f, b0 = 0.0f, a1 = 0.0f, b1 = 0.0f;
        #pragma unroll
        for (int j = 0; j < 16; j += 2) {
            unsigned ma = bits[v][j];              // broadcast LDS (scalar)
            unsigned mb = bits[v][j + 1];
            if (ma & lanebit) {                    // single LOP3 -> pred
                a0 += r0[j];
                a1 += r1[j];
            }
            if (mb & lanebit) {
                b0 += r0[j + 1];
                b1 += r1[j + 1];
            }
        }
        float acc0 = a0 + b0;
        float acc1 = a1 + b1;
        // paired-half reduction: lo half ends with sum(acc0), hi with sum(acc1)
        float fa = __shfl_xor_sync(0xffffffffu, acc0, 16);
        float fb = __shfl_xor_sync(0xffffffffu, acc1, 16);
        float x = hi_half ? (acc1 + fb) : (acc0 + fa);
        #pragma unroll
        for (int s = 8; s; s >>= 1)
            x += __shfl_xor_sync(0xffffffffu, x, s);

        // epilogue on lanes 0 (y0) and 16 (y1)
        if ((lane & 15) == 0) {
            float d   = dinv_s[v];
            float2 lw = lw2[v];
            float cbx = hi_half ? cb1 : cb0;
            float lwx = hi_half ? lw.y : lw.x;
            float h = fmaxf(fmaf(d, x, cbx), 0.0f);
            part = fmaf(h, lwx, part);
        }
    }
    if ((lane & 15) == 0) wpart[wid * 2 + (lane >> 4)] = part;
    __syncthreads();

    // ---- publish partial; 4th arrival finishes the batch ----
    if (tid == 0) {
        float p8 = ((wpart[0] + wpart[1]) + (wpart[2] + wpart[3]))
                 + ((wpart[4] + wpart[5]) + (wpart[6] + wpart[7]));
        g_part[blockIdx.x] = p8;
        __threadfence();                                    // release partial
        unsigned old = atomicAdd(&g_done[b], 1u);
        if ((old & 3u) == 3u) {                             // monotonic mod-4
            __threadfence();                                // acquire partials
            const float* p = &g_part[b * 4];
            float logit = (p[0] + p[1]) + (p[2] + p[3]) + lin_bias[0];
            out[b] = 1.0f / (1.0f + expf(-logit));
        }
    }
}

extern "C" void kernel_launch(void* const* d_in, const int* in_sizes, int n_in,
                              void* d_out, int out_size) {
    const float* features    = (const float*)d_in[0];
    const int*   graphs      = (const int*)  d_in[1];
    const float* conv_weight = (const float*)d_in[2];
    const float* conv_bias   = (const float*)d_in[3];
    const float* lin_weight  = (const float*)d_in[4];
    const float* lin_bias    = (const float*)d_in[5];
    float* out = (float*)d_out;

    gcn_rows_kernel<<<GRID_A, NTHREADS>>>(features, graphs, conv_weight);
    gcn_agg_kernel<<<BATCH * 4, 128>>>(conv_bias, lin_weight, lin_bias, out);
}

// round 17
// speedup vs baseline: 1.0573x; 1.0113x over previous
#include <cuda_runtime.h>
#include <cstdint>

// GCN FeatureDiscriminator: B=256, V=512, F=256, O=2
// A: streaming pass (round-10 exact form — measured at HBM ceiling ~61us).
// B: quarter-batch aggregation; scalar-LDS predicated-FADD body, split
//    accumulator chains, QUAD-FOLD reduction (2 rows / 4 values jointly),
//    last-CTA-done epilogue.

#define BATCH 256
#define BV 512
#define BF 256
#define NROWS (BATCH * BV)
#define NTHREADS 512
#define NWARP 16
#define GRID_A 304
#define TOTAL_WARPS_A (GRID_A * NWARP)
#define QROWS 128                     // rows per B CTA (quarter batch)

__device__ unsigned g_bits[NROWS * 16];   // 8 MB: 512-bit mask per row
__device__ float    g_dinv[NROWS];
__device__ float2   g_sxw[NROWS];         // dinv[w] * (X[w,:] @ W)
__device__ float    g_part[BATCH * 4];    // per-quarter head partials
__device__ unsigned g_done[BATCH];        // monotonic arrival counters (mod 4)

// ---------------------------------------------------------------------------
// Kernel A: warp per row, grid-stride. (round-10 exact — proven ceiling)
// Bit convention: bits[row][4c+k] bit 'l'  <->  column w = 128*c + 4*l + k
// ---------------------------------------------------------------------------
__global__ __launch_bounds__(NTHREADS, 2)
void gcn_rows_kernel(const float* __restrict__ features,
                     const int*   __restrict__ graphs,
                     const float* __restrict__ conv_weight)   // [F,2]
{
    const int tid  = threadIdx.x;
    const int wid  = tid >> 5;
    const int lane = tid & 31;
    const int gwarp = blockIdx.x * NWARP + wid;

    float w0r[8], w1r[8];
    {
        const float2* cw2 = (const float2*)conv_weight;
        #pragma unroll
        for (int j = 0; j < 8; j++) {
            float2 w = __ldg(cw2 + 8 * lane + j);
            w0r[j] = w.x; w1r[j] = w.y;
        }
    }

    for (int row = gwarp; row < NROWS; row += TOTAL_WARPS_A) {
        const int v = row & (BV - 1);
        const int4*   grow = (const int4*)graphs + (size_t)row * (BV / 4);
        const float4* frow = (const float4*)features + (size_t)row * (BF / 4);

        int4 x0 = __ldcs(grow + 0 * 32 + lane);
        int4 x1 = __ldcs(grow + 1 * 32 + lane);
        int4 x2 = __ldcs(grow + 2 * 32 + lane);
        int4 x3 = __ldcs(grow + 3 * 32 + lane);
        float4 fa = __ldcs(frow + 2 * lane);
        float4 fb = __ldcs(frow + 2 * lane + 1);

        int deg = 0;
        #pragma unroll
        for (int c = 0; c < 4; c++) {
            int4 x = (c == 0) ? x0 : (c == 1) ? x1 : (c == 2) ? x2 : x3;
            int w0 = 128 * c + 4 * lane;
            unsigned m0 = __ballot_sync(0xffffffffu, (x.x != 0) || (w0     == v));
            unsigned m1 = __ballot_sync(0xffffffffu, (x.y != 0) || (w0 + 1 == v));
            unsigned m2 = __ballot_sync(0xffffffffu, (x.z != 0) || (w0 + 2 == v));
            unsigned m3 = __ballot_sync(0xffffffffu, (x.w != 0) || (w0 + 3 == v));
            deg += __popc(m0) + __popc(m1) + __popc(m2) + __popc(m3);
            if (lane == c) {
                ((uint4*)g_bits)[(size_t)row * 4 + c] = make_uint4(m0, m1, m2, m3);
            }
        }

        float acc0 = fa.x * w0r[0];             float acc1 = fa.x * w1r[0];
        acc0 = fmaf(fa.y, w0r[1], acc0);        acc1 = fmaf(fa.y, w1r[1], acc1);
        acc0 = fmaf(fa.z, w0r[2], acc0);        acc1 = fmaf(fa.z, w1r[2], acc1);
        acc0 = fmaf(fa.w, w0r[3], acc0);        acc1 = fmaf(fa.w, w1r[3], acc1);
        acc0 = fmaf(fb.x, w0r[4], acc0);        acc1 = fmaf(fb.x, w1r[4], acc1);
        acc0 = fmaf(fb.y, w0r[5], acc0);        acc1 = fmaf(fb.y, w1r[5], acc1);
        acc0 = fmaf(fb.z, w0r[6], acc0);        acc1 = fmaf(fb.z, w1r[6], acc1);
        acc0 = fmaf(fb.w, w0r[7], acc0);        acc1 = fmaf(fb.w, w1r[7], acc1);
        #pragma unroll
        for (int s = 16; s; s >>= 1) {
            acc0 += __shfl_xor_sync(0xffffffffu, acc0, s);
            acc1 += __shfl_xor_sync(0xffffffffu, acc1, s);
        }
        if (lane == 0) {
            float d = rsqrtf((float)deg);        // deg >= 1 (self-loop)
            g_dinv[row] = d;
            g_sxw[row]  = make_float2(d * acc0, d * acc1);
        }
    }
}

// ---------------------------------------------------------------------------
// Kernel B: quarter-batch per CTA. 1024 CTAs x 128 threads, occ 8.
// Scalar-LDS body, split accumulators, quad-fold reduction (2 rows jointly),
// last-CTA-done epilogue.
// ---------------------------------------------------------------------------
__global__ __launch_bounds__(128, 8)
void gcn_agg_kernel(const float* __restrict__ conv_bias,
                    const float* __restrict__ lin_weight,    // [2v+o]
                    const float* __restrict__ lin_bias,
                    float* __restrict__ out)
{
    __shared__ unsigned bits[QROWS][16];   // 8 KB
    __shared__ float s0[BV];               // 2 KB
    __shared__ float s1[BV];               // 2 KB
    __shared__ float dinv_s[QROWS];        // 0.5 KB
    __shared__ float2 lw2[QROWS];          // 1 KB
    __shared__ float wpart[16];

    const int b    = blockIdx.x >> 2;
    const int q    = blockIdx.x & 3;
    const int tid  = threadIdx.x;
    const int wid  = tid >> 5;             // 0..3
    const int lane = tid & 31;
    const unsigned lanebit = 1u << lane;
    const bool hi_half = (lane & 16) != 0;   // selects output o
    const bool sel_b   = (lane & 8)  != 0;   // selects row B

    // ---- stage (coalesced) ----
    {
        const uint4* src = (const uint4*)g_bits + (size_t)b * (BV * 4)
                         + (size_t)q * (QROWS * 4);
        #pragma unroll
        for (int i = 0; i < 4; i++)
            ((uint4*)bits)[tid + i * 128] = src[tid + i * 128];

        #pragma unroll
        for (int i = 0; i < 4; i++) {
            float2 t = g_sxw[b * BV + tid + i * 128];   // already dinv-scaled
            s0[tid + i * 128] = t.x;
            s1[tid + i * 128] = t.y;
        }
        dinv_s[tid] = g_dinv[b * BV + q * QROWS + tid];
        lw2[tid]    = ((const float2*)lin_weight)[q * QROWS + tid];
    }
    __syncthreads();

    // preload this lane's fixed 16 s pairs: w = 128*c + 4*lane + k
    float r0[16], r1[16];
    #pragma unroll
    for (int c = 0; c < 4; c++)
        #pragma unroll
        for (int k = 0; k < 4; k++) {
            int w = 128 * c + 4 * lane + k;
            r0[4 * c + k] = s0[w];
            r1[4 * c + k] = s1[w];
        }

    const float cb0 = conv_bias[0];
    const float cb1 = conv_bias[1];

    float part = 0.0f;
    #pragma unroll 2
    for (int rp = 0; rp < QROWS / 8; rp++) {       // 16 row-pairs per warp
        const int vA = (wid << 5) + 2 * rp;
        const int vB = vA + 1;

        // --- row A: split accumulator chains ---
        float a0 = 0.0f, a0b = 0.0f, a1 = 0.0f, a1b = 0.0f;
        #pragma unroll
        for (int j = 0; j < 16; j += 2) {
            unsigned ma = bits[vA][j];
            unsigned mb = bits[vA][j + 1];
            if (ma & lanebit) { a0  += r0[j];     a1  += r1[j];     }
            if (mb & lanebit) { a0b += r0[j + 1]; a1b += r1[j + 1]; }
        }
        float A0 = a0 + a0b, A1 = a1 + a1b;

        // --- row B ---
        float c0 = 0.0f, c0b = 0.0f, c1 = 0.0f, c1b = 0.0f;
        #pragma unroll
        for (int j = 0; j < 16; j += 2) {
            unsigned ma = bits[vB][j];
            unsigned mb = bits[vB][j + 1];
            if (ma & lanebit) { c0  += r0[j];     c1  += r1[j];     }
            if (mb & lanebit) { c0b += r0[j + 1]; c1b += r1[j + 1]; }
        }
        float B0 = c0 + c0b, B1 = c1 + c1b;

        // --- quad fold: 4 values -> lanes {0,8,16,24} ---
        // fold @16, select output by hi_half
        A0 += __shfl_xor_sync(0xffffffffu, A0, 16);
        A1 += __shfl_xor_sync(0xffffffffu, A1, 16);
        B0 += __shfl_xor_sync(0xffffffffu, B0, 16);
        B1 += __shfl_xor_sync(0xffffffffu, B1, 16);
        float uA = hi_half ? A1 : A0;              // row A, output hi_half
        float uB = hi_half ? B1 : B0;              // row B, output hi_half
        // fold @8, select row by bit 3
        uA += __shfl_xor_sync(0xffffffffu, uA, 8);
        uB += __shfl_xor_sync(0xffffffffu, uB, 8);
        float x = sel_b ? uB : uA;                 // row (bit3), output (bit4)
        // 3-level butterfly within 8-lane group
        #pragma unroll
        for (int s = 4; s; s >>= 1)
            x += __shfl_xor_sync(0xffffffffu, x, s);

        // epilogue on lanes 0,8,16,24
        if ((lane & 7) == 0) {
            const int v = sel_b ? vB : vA;
            float d   = dinv_s[v];
            float2 lw = lw2[v];
            float cbx = hi_half ? cb1 : cb0;
            float lwx = hi_half ? lw.y : lw.x;
            float h = fmaxf(fmaf(d, x, cbx), 0.0f);
            part = fmaf(h, lwx, part);
        }
    }
    if ((lane & 7) == 0) wpart[wid * 4 + (lane >> 3)] = part;
    __syncthreads();

    // ---- publish partial; 4th arrival finishes the batch ----
    if (tid == 0) {
        float p = 0.0f;
        #pragma unroll
        for (int i = 0; i < 16; i++) p += wpart[i];
        g_part[blockIdx.x] = p;
        __threadfence();                                    // release partial
        unsigned old = atomicAdd(&g_done[b], 1u);
        if ((old & 3u) == 3u) {                             // monotonic mod-4
            __threadfence();                                // acquire partials
            const float* pp = &g_part[b * 4];
            float logit = (pp[0] + pp[1]) + (pp[2] + pp[3]) + lin_bias[0];
            out[b] = 1.0f / (1.0f + expf(-logit));
        }
    }
}

extern "C" void kernel_launch(void* const* d_in, const int* in_sizes, int n_in,
                              void* d_out, int out_size) {
    const float* features    = (const float*)d_in[0];
    const int*   graphs      = (const int*)  d_in[1];
    const float* conv_weight = (const float*)d_in[2];
    const float* conv_bias   = (const float*)d_in[3];
    const float* lin_weight  = (const float*)d_in[4];
    const float* lin_bias    = (const float*)d_in[5];
    float* out = (float*)d_out;

    gcn_rows_kernel<<<GRID_A, NTHREADS>>>(features, graphs, conv_weight);
    gcn_agg_kernel<<<BATCH * 4, 128>>>(conv_bias, lin_weight, lin_bias, out);
}